// round 9
// baseline (speedup 1.0000x reference)
#include <cuda_runtime.h>
#include <cuda_bf16.h>
#include <math.h>
#include <stdint.h>

// Shapes (fixed for this problem)
#define B_   64
#define Q_   64
#define T_   448
#define S_   512
#define D_   512
#define FD_  1024
#define H_   8
#define DH_  64
#define FF_  2048
#define NROWS (B_ * S_)   // 32768
#define VROWS (B_ * T_)   // 28672
#define QKVN 1536

#define NEG_INF __int_as_float(0xff800000)

// ---------------- scratch (device globals; no allocation) ----------------
__device__ float g_x [NROWS * D_];
__device__ float g_t [NROWS * D_];

// split activations (bf16 hi/lo)
__device__ __nv_bfloat16 g_ah[(size_t)VROWS * FD_];
__device__ __nv_bfloat16 g_al[(size_t)VROWS * FD_];
__device__ __nv_bfloat16 g_bh[(size_t)NROWS * FF_];
__device__ __nv_bfloat16 g_bl[(size_t)NROWS * FF_];
// fused QKV output, split
__device__ __nv_bfloat16 g_qkvh[(size_t)NROWS * QKVN];
__device__ __nv_bfloat16 g_qkvl[(size_t)NROWS * QKVN];

// transposed+split weights [N, K] bf16
__device__ __nv_bfloat16 g_wvh[512 * 1024],       g_wvl[512 * 1024];
__device__ __nv_bfloat16 g_wqkvh[2 * QKVN * 512], g_wqkvl[2 * QKVN * 512];
__device__ __nv_bfloat16 g_woh[2 * 512 * 512],    g_wol[2 * 512 * 512];
__device__ __nv_bfloat16 g_w1h[2 * 2048 * 512],   g_w1l[2 * 2048 * 512];
__device__ __nv_bfloat16 g_w2h[2 * 512 * 2048],   g_w2l[2 * 512 * 2048];
__device__ float g_bqkv[2 * QKVN];

// ---------------- helpers ----------------
__device__ __forceinline__ uint32_t smem_u32(const void* p) {
    uint32_t a;
    asm("{ .reg .u64 t; cvta.to.shared.u64 t, %1; cvt.u32.u64 %0, t; }" : "=r"(a) : "l"(p));
    return a;
}
__device__ __forceinline__ void cp16(uint32_t s, const void* g) {
    asm volatile("cp.async.cg.shared.global [%0], [%1], 16;" :: "r"(s), "l"(g));
}
#define CP_COMMIT()  asm volatile("cp.async.commit_group;" ::: "memory")
#define CP_WAIT0()   asm volatile("cp.async.wait_group 0;" ::: "memory")
#define CP_WAIT1()   asm volatile("cp.async.wait_group 1;" ::: "memory")
#define CP_WAIT2()   asm volatile("cp.async.wait_group 2;" ::: "memory")

#define LDSM4(r0, r1, r2, r3, addr) \
    asm volatile("ldmatrix.sync.aligned.m8n8.x4.shared.b16 {%0,%1,%2,%3}, [%4];" \
        : "=r"(r0), "=r"(r1), "=r"(r2), "=r"(r3) : "r"(addr))
#define LDSM4T(r0, r1, r2, r3, addr) \
    asm volatile("ldmatrix.sync.aligned.m8n8.x4.trans.shared.b16 {%0,%1,%2,%3}, [%4];" \
        : "=r"(r0), "=r"(r1), "=r"(r2), "=r"(r3) : "r"(addr))

#define MMA16816(d, a, b) \
    asm volatile("mma.sync.aligned.m16n8k16.row.col.f32.bf16.bf16.f32 " \
        "{%0,%1,%2,%3}, {%4,%5,%6,%7}, {%8,%9}, {%0,%1,%2,%3};" \
        : "+f"((d)[0]), "+f"((d)[1]), "+f"((d)[2]), "+f"((d)[3]) \
        : "r"((a)[0]), "r"((a)[1]), "r"((a)[2]), "r"((a)[3]), \
          "r"((b)[0]), "r"((b)[1]))

__device__ __forceinline__ void split1(float v, __nv_bfloat16& h, __nv_bfloat16& l) {
    h = __float2bfloat16_rn(v);
    l = __float2bfloat16_rn(v - __bfloat162float(h));
}

// ---------------- elementwise split (video input) ----------------
__global__ __launch_bounds__(256)
void split_k(const float4* __restrict__ src, __nv_bfloat162* __restrict__ hi,
             __nv_bfloat162* __restrict__ lo, int n4)
{
    for (int i = blockIdx.x * 256 + threadIdx.x; i < n4; i += gridDim.x * 256) {
        float4 v = src[i];
        __nv_bfloat16 h0, h1, h2, h3, l0, l1, l2, l3;
        split1(v.x, h0, l0); split1(v.y, h1, l1);
        split1(v.z, h2, l2); split1(v.w, h3, l3);
        hi[i * 2 + 0] = __nv_bfloat162(h0, h1);
        hi[i * 2 + 1] = __nv_bfloat162(h2, h3);
        lo[i * 2 + 0] = __nv_bfloat162(l0, l1);
        lo[i * 2 + 1] = __nv_bfloat162(l2, l3);
    }
}

// ---------------- fused weight conversion (single launch) ----------------
__device__ __forceinline__ void tsplit_tile(const float* __restrict__ W,
                                            __nv_bfloat16* __restrict__ hi,
                                            __nv_bfloat16* __restrict__ lo,
                                            int K, int N, int t)
{
    __shared__ float tile[32][33];
    int ntN = N >> 5;
    int n0 = (t % ntN) << 5, k0 = (t / ntN) << 5;
    int tid = threadIdx.x;
    int c = tid & 31;
#pragma unroll
    for (int i = 0; i < 4; i++) {
        int r = (tid >> 5) + i * 8;
        tile[r][c] = W[(size_t)(k0 + r) * N + n0 + c];
    }
    __syncthreads();
#pragma unroll
    for (int i = 0; i < 4; i++) {
        int rr = (tid >> 5) + i * 8;
        float v = tile[c][rr];
        __nv_bfloat16 h, l;
        split1(v, h, l);
        size_t o = (size_t)(n0 + rr) * K + k0 + c;
        hi[o] = h;
        lo[o] = l;
    }
}

// grid = 6668 blocks of 256
__global__ __launch_bounds__(256)
void convert_all(const float* __restrict__ Wv,
                 const float* __restrict__ Wq, const float* __restrict__ Wk,
                 const float* __restrict__ Wva, const float* __restrict__ Wo,
                 const float* __restrict__ W1, const float* __restrict__ W2,
                 const float* __restrict__ bq, const float* __restrict__ bk,
                 const float* __restrict__ bv,
                 __nv_bfloat16* __restrict__ wvh, __nv_bfloat16* __restrict__ wvl,
                 __nv_bfloat16* __restrict__ wqkvh, __nv_bfloat16* __restrict__ wqkvl,
                 __nv_bfloat16* __restrict__ woh, __nv_bfloat16* __restrict__ wol,
                 __nv_bfloat16* __restrict__ w1h, __nv_bfloat16* __restrict__ w1l,
                 __nv_bfloat16* __restrict__ w2h, __nv_bfloat16* __restrict__ w2l,
                 float* __restrict__ bqkv)
{
    int t = blockIdx.x;
    if (t < 512) { tsplit_tile(Wv, wvh, wvl, 1024, 512, t); return; }
    t -= 512;
    if (t < 6144) {
        int i = t / 3072, u = t % 3072;
        size_t od = (size_t)i * 512 * 512;
        size_t oq = (size_t)i * QKVN * 512;
        size_t of = (size_t)i * 512 * 2048;
        if (u < 256)        tsplit_tile(Wq  + od, wqkvh + oq,              wqkvl + oq,              512, 512, u);
        else if (u < 512)   tsplit_tile(Wk  + od, wqkvh + oq + 262144,     wqkvl + oq + 262144,     512, 512, u - 256);
        else if (u < 768)   tsplit_tile(Wva + od, wqkvh + oq + 524288,     wqkvl + oq + 524288,     512, 512, u - 512);
        else if (u < 1024)  tsplit_tile(Wo  + od, woh + od, wol + od, 512, 512, u - 768);
        else if (u < 2048)  tsplit_tile(W1 + of, w1h + of, w1l + of, 512, 2048, u - 1024);
        else                tsplit_tile(W2 + of, w2h + of, w2l + of, 2048, 512, u - 2048);
        return;
    }
    t -= 6144;
    int idx = t * 256 + threadIdx.x;      // 0..3071
    if (idx < 2 * QKVN) {
        int i = idx / QKVN, j = idx % QKVN;
        float v = (j < 512) ? bq[i * 512 + j]
                : (j < 1024) ? bk[i * 512 + j - 512]
                : bv[i * 512 + j - 1024];
        bqkv[idx] = v;
    }
}

// ---------------- mma.sync split-bf16 GEMM (3-stage pipeline) ----------------
#define MG_ROWH 40
#define MG_MATH (128 * MG_ROWH)
#define MG_MATB (MG_MATH * 2)
#define MG_STGB (4 * MG_MATB)
#define MG_SMEM (3 * MG_STGB)     // 122880

__device__ __forceinline__ void mg_load(uint32_t s0,
    const __nv_bfloat16* __restrict__ Ah, const __nv_bfloat16* __restrict__ Al,
    const __nv_bfloat16* __restrict__ Bh, const __nv_bfloat16* __restrict__ Bl,
    int bm, int bn, int K, int k0, int tid)
{
#pragma unroll
    for (int i = 0; i < 2; i++) {
        int u = tid + (i << 8);
        int r = u >> 2, c8 = (u & 3) << 3;
        size_t ga = (size_t)(bm + r) * K + k0 + c8;
        size_t gb = (size_t)(bn + r) * K + k0 + c8;
        uint32_t s = s0 + (uint32_t)(r * MG_ROWH + c8) * 2;
        cp16(s,               Ah + ga);
        cp16(s + MG_MATB,     Al + ga);
        cp16(s + 2 * MG_MATB, Bh + gb);
        cp16(s + 3 * MG_MATB, Bl + gb);
    }
}

template<bool GELU, bool RES, bool SPLIT>
__global__ __launch_bounds__(256, 1)
void mgemm(const __nv_bfloat16* __restrict__ Ah, const __nv_bfloat16* __restrict__ Al,
           const __nv_bfloat16* __restrict__ Bh, const __nv_bfloat16* __restrict__ Bl,
           const float* __restrict__ bias, const float* __restrict__ res,
           float* __restrict__ C, __nv_bfloat16* __restrict__ Ch,
           __nv_bfloat16* __restrict__ Cl, int M, int N, int K)
{
    extern __shared__ char smem[];
    const uint32_t sbase = smem_u32(smem);
    const int tid = threadIdx.x;
    const int lane = tid & 31, wid = tid >> 5;
    const int wm = wid >> 1, wn = wid & 1;
    const int bn = blockIdx.x * 128, bm = blockIdx.y * 128;

    float acc[2][8][4];
#pragma unroll
    for (int i = 0; i < 2; i++)
#pragma unroll
        for (int j = 0; j < 8; j++)
#pragma unroll
            for (int p = 0; p < 4; p++) acc[i][j][p] = 0.f;

    const int a_r  = (lane < 16) ? lane : (lane - 16);
    const int a_k  = (lane < 16) ? 0 : 8;
    const int b_r  = ((lane >> 4) << 3) + (lane & 7);
    const int b_k  = ((lane >> 3) & 1) << 3;

    const int NC = K >> 5;
    mg_load(sbase, Ah, Al, Bh, Bl, bm, bn, K, 0, tid);
    CP_COMMIT();
    if (NC > 1) {
        mg_load(sbase + MG_STGB, Ah, Al, Bh, Bl, bm, bn, K, 32, tid);
        CP_COMMIT();
    }

    for (int c = 0; c < NC; c++) {
        if (c + 2 < NC) {
            int st = (c + 2) % 3;
            mg_load(sbase + st * MG_STGB, Ah, Al, Bh, Bl, bm, bn, K, (c + 2) << 5, tid);
            CP_COMMIT();
            CP_WAIT2();
        } else if (c + 1 < NC) {
            CP_WAIT1();
        } else {
            CP_WAIT0();
        }
        __syncthreads();

        const uint32_t s0  = sbase + (c % 3) * MG_STGB;
        const uint32_t aH  = s0;
        const uint32_t aL  = s0 + MG_MATB;
        const uint32_t bH  = s0 + 2 * MG_MATB;
        const uint32_t bL  = s0 + 3 * MG_MATB;

#pragma unroll
        for (int ks = 0; ks < 2; ks++) {
            uint32_t bhf[8][2], blf[8][2];
#pragma unroll
            for (int nb2 = 0; nb2 < 4; nb2++) {
                int row = wn * 64 + nb2 * 16 + b_r;
                int kof = ks * 16 + b_k;
                uint32_t off = (uint32_t)(row * MG_ROWH + kof) * 2;
                uint32_t r0, r1, r2, r3;
                LDSM4(r0, r1, r2, r3, bH + off);
                bhf[nb2 * 2][0] = r0; bhf[nb2 * 2][1] = r1;
                bhf[nb2 * 2 + 1][0] = r2; bhf[nb2 * 2 + 1][1] = r3;
                LDSM4(r0, r1, r2, r3, bL + off);
                blf[nb2 * 2][0] = r0; blf[nb2 * 2][1] = r1;
                blf[nb2 * 2 + 1][0] = r2; blf[nb2 * 2 + 1][1] = r3;
            }
#pragma unroll
            for (int mh = 0; mh < 2; mh++) {
                int row = wm * 32 + mh * 16 + a_r;
                int kof = ks * 16 + a_k;
                uint32_t off = (uint32_t)(row * MG_ROWH + kof) * 2;
                uint32_t ahf[4], alf[4];
                LDSM4(ahf[0], ahf[1], ahf[2], ahf[3], aH + off);
                LDSM4(alf[0], alf[1], alf[2], alf[3], aL + off);
#pragma unroll
                for (int nb = 0; nb < 8; nb++) {
                    MMA16816(acc[mh][nb], ahf, bhf[nb]);
                    MMA16816(acc[mh][nb], ahf, blf[nb]);
                    MMA16816(acc[mh][nb], alf, bhf[nb]);
                }
            }
        }
        __syncthreads();
    }

    const int g = lane >> 2, t4 = lane & 3;
#pragma unroll
    for (int mh = 0; mh < 2; mh++) {
#pragma unroll
        for (int nb = 0; nb < 8; nb++) {
            int col = bn + wn * 64 + nb * 8 + t4 * 2;
            float b0 = bias[col], b1 = bias[col + 1];
#pragma unroll
            for (int hf = 0; hf < 2; hf++) {
                int row = bm + wm * 32 + mh * 16 + g + hf * 8;
                float v0 = acc[mh][nb][hf * 2 + 0] + b0;
                float v1 = acc[mh][nb][hf * 2 + 1] + b1;
                if (RES) {
                    float2 rv = *(const float2*)(res + (size_t)row * N + col);
                    v0 += rv.x; v1 += rv.y;
                }
                if (GELU) {
                    v0 = 0.5f * v0 * (1.0f + erff(v0 * 0.70710678118654752f));
                    v1 = 0.5f * v1 * (1.0f + erff(v1 * 0.70710678118654752f));
                }
                if (SPLIT) {
                    __nv_bfloat16 h0, h1, l0, l1;
                    split1(v0, h0, l0);
                    split1(v1, h1, l1);
                    size_t o = (size_t)row * N + col;
                    *(__nv_bfloat162*)(Ch + o) = __nv_bfloat162(h0, h1);
                    *(__nv_bfloat162*)(Cl + o) = __nv_bfloat162(l0, l1);
                } else {
                    *(float2*)(C + (size_t)row * N + col) = make_float2(v0, v1);
                }
            }
        }
    }
}

// ---------------- block reduction ----------------
__device__ __forceinline__ float block_sum256(float v, float* red) {
    int lane = threadIdx.x & 31;
    int w    = threadIdx.x >> 5;
#pragma unroll
    for (int o = 16; o > 0; o >>= 1) v += __shfl_xor_sync(0xffffffffu, v, o);
    if (lane == 0) red[w] = v;
    __syncthreads();
    if (w == 0) {
        float r = (lane < 8) ? red[lane] : 0.f;
#pragma unroll
        for (int o = 4; o > 0; o >>= 1) r += __shfl_xor_sync(0xffffffffu, r, o);
        if (lane == 0) red[0] = r;
    }
    __syncthreads();
    float out = red[0];
    __syncthreads();
    return out;
}

// ---------------- LayerNorm over D=512 + optional split output ----------------
template<bool SPLIT>
__global__ __launch_bounds__(256)
void ln512(const float* __restrict__ in, const float* __restrict__ g,
           const float* __restrict__ b, float* __restrict__ out,
           __nv_bfloat16* __restrict__ oh, __nv_bfloat16* __restrict__ ol)
{
    __shared__ float red[32];
    size_t row = blockIdx.x;
    const float* x = in + row * D_;
    int c0 = threadIdx.x, c1 = threadIdx.x + 256;
    float v0 = x[c0], v1 = x[c1];
    float mean = block_sum256(v0 + v1, red) * (1.f / 512.f);
    float d0 = v0 - mean, d1 = v1 - mean;
    float var = block_sum256(d0 * d0 + d1 * d1, red) * (1.f / 512.f);
    float inv = 1.f / sqrtf(var + 1e-12f);
    float r0 = d0 * inv * g[c0] + b[c0];
    float r1 = d1 * inv * g[c1] + b[c1];
    out[row * D_ + c0] = r0;
    out[row * D_ + c1] = r1;
    if (SPLIT) {
        __nv_bfloat16 h0, h1, l0, l1;
        split1(r0, h0, l0);
        split1(r1, h1, l1);
        oh[row * D_ + c0] = h0; oh[row * D_ + c1] = h1;
        ol[row * D_ + c0] = l0; ol[row * D_ + c1] = l1;
    }
}

// ---------------- assemble x = LN(concat(q, v) + pos + mod), split out ----------------
__global__ __launch_bounds__(256)
void assemble_ln(const float* __restrict__ question, const float* __restrict__ vproj,
                 const float* __restrict__ pos, const float* __restrict__ mod,
                 const float* __restrict__ g, const float* __restrict__ bb,
                 float* __restrict__ out, __nv_bfloat16* __restrict__ oh,
                 __nv_bfloat16* __restrict__ ol)
{
    __shared__ float red[32];
    int row = blockIdx.x;
    int b = row >> 9, s = row & 511;
    int c0 = threadIdx.x, c1 = threadIdx.x + 256;
    float v0, v1;
    if (s < Q_) {
        const float* src = question + ((size_t)b * Q_ + s) * D_;
        v0 = src[c0]; v1 = src[c1];
    } else {
        const float* src = vproj + ((size_t)b * T_ + (s - Q_)) * D_;
        v0 = src[c0]; v1 = src[c1];
    }
    const float* me = mod + (s < Q_ ? 0 : 1) * D_;
    v0 += pos[s * D_ + c0] + me[c0];
    v1 += pos[s * D_ + c1] + me[c1];
    float mean = block_sum256(v0 + v1, red) * (1.f / 512.f);
    float d0 = v0 - mean, d1 = v1 - mean;
    float var = block_sum256(d0 * d0 + d1 * d1, red) * (1.f / 512.f);
    float inv = 1.f / sqrtf(var + 1e-12f);
    float r0 = d0 * inv * g[c0] + bb[c0];
    float r1 = d1 * inv * g[c1] + bb[c1];
    size_t o = (size_t)row * D_;
    out[o + c0] = r0;
    out[o + c1] = r1;
    __nv_bfloat16 h0, h1, l0, l1;
    split1(r0, h0, l0);
    split1(r1, h1, l1);
    oh[o + c0] = h0; oh[o + c1] = h1;
    ol[o + c0] = l0; ol[o + c1] = l1;
}

// ---------------- mma.sync flash attention (split bf16, double-buffered KV) ----------------
#define AT_ST 72
#define AT_MATB (64 * AT_ST * 2)     // 9216 bytes per matrix tile
#define ATTN_SMEM (10 * AT_MATB + 512)

__global__ __launch_bounds__(128)
void attn_mma(const __nv_bfloat16* __restrict__ QKVh, const __nv_bfloat16* __restrict__ QKVl,
              const int* __restrict__ mask,
              __nv_bfloat16* __restrict__ Oh, __nv_bfloat16* __restrict__ Ol)
{
    extern __shared__ char sm8[];
    const uint32_t sb = smem_u32(sm8);
    const uint32_t sQH = sb, sQL = sb + AT_MATB;
    const uint32_t sKV = sb + 2 * AT_MATB;           // stage s: +s*4*AT_MATB (KH,KL,VH,VL)
    int (*maskS)[64] = (int(*)[64])(sm8 + 10 * AT_MATB);

    const int qt = blockIdx.x, h = blockIdx.y, b = blockIdx.z;
    const int tid = threadIdx.x, lane = tid & 31, wq = tid >> 5;
    const int g = lane >> 2, t4 = lane & 3;

    const int a_r = (lane < 16) ? lane : lane - 16;
    const int a_k = (lane < 16) ? 0 : 8;
    const int b_r = ((lane >> 4) << 3) + (lane & 7);
    const int b_k = ((lane >> 3) & 1) << 3;
    const int v_r = (lane & 7) + (((lane >> 3) & 1) << 3);
    const int v_n = ((lane >> 4) & 1) << 3;

    // prologue: Q tile + KV tile 0 in one commit group
#pragma unroll
    for (int i = 0; i < 4; i++) {
        int u = tid + i * 128;
        int r = u >> 3, c8 = (u & 7) << 3;
        size_t gofs = (size_t)(b * S_ + qt * 64 + r) * QKVN + h * DH_ + c8;
        uint32_t so = (uint32_t)(r * AT_ST + c8) * 2;
        cp16(sQH + so, QKVh + gofs);
        cp16(sQL + so, QKVl + gofs);
    }
#pragma unroll
    for (int i = 0; i < 4; i++) {
        int u = tid + i * 128;
        int r = u >> 3, c8 = (u & 7) << 3;
        size_t grow = (size_t)(b * S_ + r) * QKVN + h * DH_;
        uint32_t so = (uint32_t)(r * AT_ST + c8) * 2;
        cp16(sKV + so,               QKVh + grow + 512 + c8);
        cp16(sKV + AT_MATB + so,     QKVl + grow + 512 + c8);
        cp16(sKV + 2 * AT_MATB + so, QKVh + grow + 1024 + c8);
        cp16(sKV + 3 * AT_MATB + so, QKVl + grow + 1024 + c8);
    }
    if (tid < 64) maskS[0][tid] = mask[b * S_ + tid];
    CP_COMMIT();

    float oacc[8][4];
#pragma unroll
    for (int i = 0; i < 8; i++)
#pragma unroll
        for (int j = 0; j < 4; j++) oacc[i][j] = 0.f;
    float m0 = NEG_INF, m1 = NEG_INF, l0 = 0.f, l1 = 0.f;

    for (int kt = 0; kt < 8; kt++) {
        __syncthreads();   // all warps done reading stage (kt+1)&1 (from kt-1)
        if (kt + 1 < 8) {
            int st = (kt + 1) & 1;
            uint32_t sbKV = sKV + st * 4 * AT_MATB;
#pragma unroll
            for (int i = 0; i < 4; i++) {
                int u = tid + i * 128;
                int r = u >> 3, c8 = (u & 7) << 3;
                size_t grow = (size_t)(b * S_ + (kt + 1) * 64 + r) * QKVN + h * DH_;
                uint32_t so = (uint32_t)(r * AT_ST + c8) * 2;
                cp16(sbKV + so,               QKVh + grow + 512 + c8);
                cp16(sbKV + AT_MATB + so,     QKVl + grow + 512 + c8);
                cp16(sbKV + 2 * AT_MATB + so, QKVh + grow + 1024 + c8);
                cp16(sbKV + 3 * AT_MATB + so, QKVl + grow + 1024 + c8);
            }
            if (tid < 64) maskS[st][tid] = mask[b * S_ + (kt + 1) * 64 + tid];
            CP_COMMIT();
            CP_WAIT1();
        } else {
            CP_WAIT0();
        }
        __syncthreads();

        const int cs = kt & 1;
        const uint32_t sKH = sKV + cs * 4 * AT_MATB;
        const uint32_t sKL = sKH + AT_MATB;
        const uint32_t sVH = sKH + 2 * AT_MATB;
        const uint32_t sVL = sKH + 3 * AT_MATB;
        const int* mrow = maskS[cs];

        // ---- scores: S = Q K^T (split, 3 MMA) ----
        float sacc[8][4];
#pragma unroll
        for (int i = 0; i < 8; i++)
#pragma unroll
            for (int j = 0; j < 4; j++) sacc[i][j] = 0.f;

#pragma unroll
        for (int ks = 0; ks < 4; ks++) {
            uint32_t qh[4], ql[4];
            uint32_t qoff = (uint32_t)((wq * 16 + a_r) * AT_ST + ks * 16 + a_k) * 2;
            LDSM4(qh[0], qh[1], qh[2], qh[3], sQH + qoff);
            LDSM4(ql[0], ql[1], ql[2], ql[3], sQL + qoff);
#pragma unroll
            for (int nb2 = 0; nb2 < 4; nb2++) {
                uint32_t kh[4], kl[4];
                uint32_t koff = (uint32_t)((nb2 * 16 + b_r) * AT_ST + ks * 16 + b_k) * 2;
                LDSM4(kh[0], kh[1], kh[2], kh[3], sKH + koff);
                LDSM4(kl[0], kl[1], kl[2], kl[3], sKL + koff);
                uint32_t f0[2] = {kh[0], kh[1]}, f1[2] = {kh[2], kh[3]};
                uint32_t e0[2] = {kl[0], kl[1]}, e1[2] = {kl[2], kl[3]};
                MMA16816(sacc[nb2 * 2],     qh, f0);
                MMA16816(sacc[nb2 * 2],     qh, e0);
                MMA16816(sacc[nb2 * 2],     ql, f0);
                MMA16816(sacc[nb2 * 2 + 1], qh, f1);
                MMA16816(sacc[nb2 * 2 + 1], qh, e1);
                MMA16816(sacc[nb2 * 2 + 1], ql, f1);
            }
        }

        // ---- scale + mask ----
#pragma unroll
        for (int nb = 0; nb < 8; nb++) {
            int c = (nb << 3) + (t4 << 1);
            bool z0 = (mrow[c] == 0), z1 = (mrow[c + 1] == 0);
            sacc[nb][0] = z0 ? NEG_INF : sacc[nb][0] * 0.125f;
            sacc[nb][1] = z1 ? NEG_INF : sacc[nb][1] * 0.125f;
            sacc[nb][2] = z0 ? NEG_INF : sacc[nb][2] * 0.125f;
            sacc[nb][3] = z1 ? NEG_INF : sacc[nb][3] * 0.125f;
        }

        // ---- online softmax (rows g and g+8) ----
        float t0 = NEG_INF, t1 = NEG_INF;
#pragma unroll
        for (int nb = 0; nb < 8; nb++) {
            t0 = fmaxf(t0, fmaxf(sacc[nb][0], sacc[nb][1]));
            t1 = fmaxf(t1, fmaxf(sacc[nb][2], sacc[nb][3]));
        }
        t0 = fmaxf(t0, __shfl_xor_sync(0xffffffffu, t0, 1));
        t0 = fmaxf(t0, __shfl_xor_sync(0xffffffffu, t0, 2));
        t1 = fmaxf(t1, __shfl_xor_sync(0xffffffffu, t1, 1));
        t1 = fmaxf(t1, __shfl_xor_sync(0xffffffffu, t1, 2));
        float m0n = fmaxf(m0, t0), m1n = fmaxf(m1, t1);
        float me0 = (m0n == NEG_INF) ? 0.f : m0n;
        float me1 = (m1n == NEG_INF) ? 0.f : m1n;
        float alpha0 = __expf(m0 - me0);
        float alpha1 = __expf(m1 - me1);
        m0 = m0n; m1 = m1n;

        float s0 = 0.f, s1 = 0.f;
#pragma unroll
        for (int nb = 0; nb < 8; nb++) {
            float p0 = (sacc[nb][0] == NEG_INF) ? 0.f : __expf(sacc[nb][0] - me0);
            float p1 = (sacc[nb][1] == NEG_INF) ? 0.f : __expf(sacc[nb][1] - me0);
            float p2 = (sacc[nb][2] == NEG_INF) ? 0.f : __expf(sacc[nb][2] - me1);
            float p3 = (sacc[nb][3] == NEG_INF) ? 0.f : __expf(sacc[nb][3] - me1);
            sacc[nb][0] = p0; sacc[nb][1] = p1; sacc[nb][2] = p2; sacc[nb][3] = p3;
            s0 += p0 + p1; s1 += p2 + p3;
        }
        s0 += __shfl_xor_sync(0xffffffffu, s0, 1);
        s0 += __shfl_xor_sync(0xffffffffu, s0, 2);
        s1 += __shfl_xor_sync(0xffffffffu, s1, 1);
        s1 += __shfl_xor_sync(0xffffffffu, s1, 2);
        l0 = l0 * alpha0 + s0;
        l1 = l1 * alpha1 + s1;
#pragma unroll
        for (int nb = 0; nb < 8; nb++) {
            oacc[nb][0] *= alpha0; oacc[nb][1] *= alpha0;
            oacc[nb][2] *= alpha1; oacc[nb][3] *= alpha1;
        }

        // ---- O += P V (split P, split V, 3 MMA) ----
#pragma unroll
        for (int ks = 0; ks < 4; ks++) {
            const float* sa = sacc[2 * ks];
            const float* sc = sacc[2 * ks + 1];
            uint32_t ph[4], pl[4];
            {
                __nv_bfloat16 h0, l0b, h1, l1b;
                split1(sa[0], h0, l0b); split1(sa[1], h1, l1b);
                ph[0] = ((uint32_t)*(uint16_t*)&h1 << 16) | *(uint16_t*)&h0;
                pl[0] = ((uint32_t)*(uint16_t*)&l1b << 16) | *(uint16_t*)&l0b;
                split1(sa[2], h0, l0b); split1(sa[3], h1, l1b);
                ph[1] = ((uint32_t)*(uint16_t*)&h1 << 16) | *(uint16_t*)&h0;
                pl[1] = ((uint32_t)*(uint16_t*)&l1b << 16) | *(uint16_t*)&l0b;
                split1(sc[0], h0, l0b); split1(sc[1], h1, l1b);
                ph[2] = ((uint32_t)*(uint16_t*)&h1 << 16) | *(uint16_t*)&h0;
                pl[2] = ((uint32_t)*(uint16_t*)&l1b << 16) | *(uint16_t*)&l0b;
                split1(sc[2], h0, l0b); split1(sc[3], h1, l1b);
                ph[3] = ((uint32_t)*(uint16_t*)&h1 << 16) | *(uint16_t*)&h0;
                pl[3] = ((uint32_t)*(uint16_t*)&l1b << 16) | *(uint16_t*)&l0b;
            }
#pragma unroll
            for (int nb2 = 0; nb2 < 4; nb2++) {
                uint32_t vh[4], vl[4];
                uint32_t voff = (uint32_t)((ks * 16 + v_r) * AT_ST + nb2 * 16 + v_n) * 2;
                LDSM4T(vh[0], vh[1], vh[2], vh[3], sVH + voff);
                LDSM4T(vl[0], vl[1], vl[2], vl[3], sVL + voff);
                uint32_t f0[2] = {vh[0], vh[1]}, f1[2] = {vh[2], vh[3]};
                uint32_t e0[2] = {vl[0], vl[1]}, e1[2] = {vl[2], vl[3]};
                MMA16816(oacc[nb2 * 2],     ph, f0);
                MMA16816(oacc[nb2 * 2],     ph, e0);
                MMA16816(oacc[nb2 * 2],     pl, f0);
                MMA16816(oacc[nb2 * 2 + 1], ph, f1);
                MMA16816(oacc[nb2 * 2 + 1], ph, e1);
                MMA16816(oacc[nb2 * 2 + 1], pl, f1);
            }
        }
    }

    // ---- epilogue: O/l, split, store ctx ----
    float inv0 = 1.f / l0, inv1 = 1.f / l1;
    int row0 = b * S_ + qt * 64 + wq * 16 + g;
#pragma unroll
    for (int nb = 0; nb < 8; nb++) {
        int col = h * DH_ + nb * 8 + t4 * 2;
        float v0 = oacc[nb][0] * inv0, v1 = oacc[nb][1] * inv0;
        float v2 = oacc[nb][2] * inv1, v3 = oacc[nb][3] * inv1;
        __nv_bfloat16 h0, l0b, h1, l1b;
        split1(v0, h0, l0b); split1(v1, h1, l1b);
        *(__nv_bfloat162*)(Oh + (size_t)row0 * D_ + col) = __nv_bfloat162(h0, h1);
        *(__nv_bfloat162*)(Ol + (size_t)row0 * D_ + col) = __nv_bfloat162(l0b, l1b);
        split1(v2, h0, l0b); split1(v3, h1, l1b);
        *(__nv_bfloat162*)(Oh + (size_t)(row0 + 8) * D_ + col) = __nv_bfloat162(h0, h1);
        *(__nv_bfloat162*)(Ol + (size_t)(row0 + 8) * D_ + col) = __nv_bfloat162(l0b, l1b);
    }
}

// ---------------- orchestration ----------------
extern "C" void kernel_launch(void* const* d_in, const int* in_sizes, int n_in,
                              void* d_out, int out_size)
{
    (void)in_sizes; (void)n_in; (void)out_size;
    const float* video    = (const float*)d_in[0];
    const float* question = (const float*)d_in[1];
    const int*   mask     = (const int*)  d_in[2];
    const float* pos_emb  = (const float*)d_in[3];
    const float* mod_emb  = (const float*)d_in[4];
    const float* Wv   = (const float*)d_in[5];
    const float* bv   = (const float*)d_in[6];
    const float* nv_g = (const float*)d_in[7];
    const float* nv_b = (const float*)d_in[8];
    const float* emb_g= (const float*)d_in[9];
    const float* emb_b= (const float*)d_in[10];
    const float* Wq   = (const float*)d_in[11];
    const float* bq   = (const float*)d_in[12];
    const float* Wk   = (const float*)d_in[13];
    const float* bk   = (const float*)d_in[14];
    const float* Wva  = (const float*)d_in[15];
    const float* bva  = (const float*)d_in[16];
    const float* Wo   = (const float*)d_in[17];
    const float* bo   = (const float*)d_in[18];
    const float* ln1_g= (const float*)d_in[19];
    const float* ln1_b= (const float*)d_in[20];
    const float* W1   = (const float*)d_in[21];
    const float* b1   = (const float*)d_in[22];
    const float* W2   = (const float*)d_in[23];
    const float* b2   = (const float*)d_in[24];
    const float* ln2_g= (const float*)d_in[25];
    const float* ln2_b= (const float*)d_in[26];

    float *x, *t, *bqkv;
    cudaGetSymbolAddress((void**)&x, g_x);
    cudaGetSymbolAddress((void**)&t, g_t);
    cudaGetSymbolAddress((void**)&bqkv, g_bqkv);

    __nv_bfloat16 *ah, *al, *bh, *bl, *qkvh, *qkvl, *wvh, *wvl, *wqkvh, *wqkvl,
                  *woh, *wol, *w1h, *w1l, *w2h, *w2l;
    cudaGetSymbolAddress((void**)&ah,    g_ah);
    cudaGetSymbolAddress((void**)&al,    g_al);
    cudaGetSymbolAddress((void**)&bh,    g_bh);
    cudaGetSymbolAddress((void**)&bl,    g_bl);
    cudaGetSymbolAddress((void**)&qkvh,  g_qkvh);
    cudaGetSymbolAddress((void**)&qkvl,  g_qkvl);
    cudaGetSymbolAddress((void**)&wvh,   g_wvh);
    cudaGetSymbolAddress((void**)&wvl,   g_wvl);
    cudaGetSymbolAddress((void**)&wqkvh, g_wqkvh);
    cudaGetSymbolAddress((void**)&wqkvl, g_wqkvl);
    cudaGetSymbolAddress((void**)&woh,   g_woh);
    cudaGetSymbolAddress((void**)&wol,   g_wol);
    cudaGetSymbolAddress((void**)&w1h,   g_w1h);
    cudaGetSymbolAddress((void**)&w1l,   g_w1l);
    cudaGetSymbolAddress((void**)&w2h,   g_w2h);
    cudaGetSymbolAddress((void**)&w2l,   g_w2l);

    cudaFuncSetAttribute(attn_mma, cudaFuncAttributeMaxDynamicSharedMemorySize, ATTN_SMEM);
    cudaFuncSetAttribute(mgemm<false, false, false>, cudaFuncAttributeMaxDynamicSharedMemorySize, MG_SMEM);
    cudaFuncSetAttribute(mgemm<false, true,  false>, cudaFuncAttributeMaxDynamicSharedMemorySize, MG_SMEM);
    cudaFuncSetAttribute(mgemm<true,  false, true >, cudaFuncAttributeMaxDynamicSharedMemorySize, MG_SMEM);
    cudaFuncSetAttribute(mgemm<false, false, true >, cudaFuncAttributeMaxDynamicSharedMemorySize, MG_SMEM);

    // (1) all weight conversion in ONE launch
    convert_all<<<6668, 256>>>(Wv, Wq, Wk, Wva, Wo, W1, W2, bq, bk, bva,
                               wvh, wvl, wqkvh, wqkvl, woh, wol,
                               w1h, w1l, w2h, w2l, bqkv);

    // (2) video split, (3) video projection, (4) LN(nv), (5) assemble
    split_k<<<2048, 256>>>((const float4*)video, (__nv_bfloat162*)ah,
                           (__nv_bfloat162*)al, (int)((size_t)VROWS * FD_ / 4));
    mgemm<false, false, false><<<dim3(D_ / 128, VROWS / 128), 256, MG_SMEM>>>(
        ah, al, wvh, wvl, bv, nullptr, t, nullptr, nullptr, VROWS, D_, FD_);
    ln512<false><<<VROWS, 256>>>(t, nv_g, nv_b, t, nullptr, nullptr);
    assemble_ln<<<NROWS, 256>>>(question, t, pos_emb, mod_emb, emb_g, emb_b, x, ah, al);

    for (int i = 0; i < 2; i++) {
        size_t od = (size_t)i * 512 * 512;
        size_t oq = (size_t)i * QKVN * 512;
        size_t of = (size_t)i * 512 * 2048;
        const float* boi = bo + i * D_;
        const float* b1i = b1 + i * FF_;
        const float* b2i = b2 + i * D_;

        // (6) fused QKV projection (split output)  <- ncu -s 5 lands here
        mgemm<false, false, true><<<dim3(QKVN / 128, NROWS / 128), 256, MG_SMEM>>>(
            ah, al, wqkvh + oq, wqkvl + oq, bqkv + i * QKVN, nullptr,
            nullptr, qkvh, qkvl, NROWS, QKVN, D_);

        // attention -> ctx split (bh/bl viewed [NROWS, D])
        attn_mma<<<dim3(S_ / 64, H_, B_), 128, ATTN_SMEM>>>(qkvh, qkvl, mask, bh, bl);

        // output projection + residual, LN1 (-> x fp32 + ah/al split)
        mgemm<false, true, false><<<dim3(4, NROWS / 128), 256, MG_SMEM>>>(
            bh, bl, woh + od, wol + od, boi, x, t, nullptr, nullptr, NROWS, D_, D_);
        ln512<true><<<NROWS, 256>>>(t, ln1_g + i * D_, ln1_b + i * D_, x, ah, al);

        // FFN
        mgemm<true, false, true><<<dim3(FF_ / 128, NROWS / 128), 256, MG_SMEM>>>(
            ah, al, w1h + of, w1l + of, b1i, nullptr, nullptr, bh, bl, NROWS, FF_, D_);
        mgemm<false, true, false><<<dim3(4, NROWS / 128), 256, MG_SMEM>>>(
            bh, bl, w2h + of, w2l + of, b2i, x, t, nullptr, nullptr, NROWS, D_, FF_);

        float* out = (i == 1) ? (float*)d_out : x;
        ln512<true><<<NROWS, 256>>>(t, ln2_g + i * D_, ln2_b + i * D_, out, ah, al);
    }
}

// round 14
// speedup vs baseline: 1.2193x; 1.2193x over previous
#include <cuda_runtime.h>
#include <cuda_bf16.h>
#include <math.h>
#include <stdint.h>

// Shapes (fixed for this problem)
#define B_   64
#define Q_   64
#define T_   448
#define S_   512
#define D_   512
#define FD_  1024
#define H_   8
#define DH_  64
#define FF_  2048
#define NROWS (B_ * S_)   // 32768
#define VROWS (B_ * T_)   // 28672
#define QKVN 1536

#define NEG_INF __int_as_float(0xff800000)

// ---------------- scratch (device globals; no allocation) ----------------
__device__ float g_x [NROWS * D_];
__device__ float g_t [NROWS * D_];

// split activations (bf16 hi/lo)
__device__ __nv_bfloat16 g_ah[(size_t)VROWS * FD_];
__device__ __nv_bfloat16 g_al[(size_t)VROWS * FD_];
__device__ __nv_bfloat16 g_bh[(size_t)NROWS * FF_];
__device__ __nv_bfloat16 g_bl[(size_t)NROWS * FF_];
// fused QKV output, split
__device__ __nv_bfloat16 g_qkvh[(size_t)NROWS * QKVN];
__device__ __nv_bfloat16 g_qkvl[(size_t)NROWS * QKVN];

// transposed+split weights [N, K] bf16
__device__ __nv_bfloat16 g_wvh[512 * 1024],       g_wvl[512 * 1024];
__device__ __nv_bfloat16 g_wqkvh[2 * QKVN * 512], g_wqkvl[2 * QKVN * 512];
__device__ __nv_bfloat16 g_woh[2 * 512 * 512],    g_wol[2 * 512 * 512];
__device__ __nv_bfloat16 g_w1h[2 * 2048 * 512],   g_w1l[2 * 2048 * 512];
__device__ __nv_bfloat16 g_w2h[2 * 512 * 2048],   g_w2l[2 * 512 * 2048];
__device__ float g_bqkv[2 * QKVN];

// ---------------- helpers ----------------
__device__ __forceinline__ uint32_t smem_u32(const void* p) {
    uint32_t a;
    asm("{ .reg .u64 t; cvta.to.shared.u64 t, %1; cvt.u32.u64 %0, t; }" : "=r"(a) : "l"(p));
    return a;
}
__device__ __forceinline__ void cp16(uint32_t s, const void* g) {
    asm volatile("cp.async.cg.shared.global [%0], [%1], 16;" :: "r"(s), "l"(g));
}
#define CP_COMMIT()  asm volatile("cp.async.commit_group;" ::: "memory")
#define CP_WAIT0()   asm volatile("cp.async.wait_group 0;" ::: "memory")
#define CP_WAIT1()   asm volatile("cp.async.wait_group 1;" ::: "memory")

#define LDSM4(r0, r1, r2, r3, addr) \
    asm volatile("ldmatrix.sync.aligned.m8n8.x4.shared.b16 {%0,%1,%2,%3}, [%4];" \
        : "=r"(r0), "=r"(r1), "=r"(r2), "=r"(r3) : "r"(addr))
#define LDSM4T(r0, r1, r2, r3, addr) \
    asm volatile("ldmatrix.sync.aligned.m8n8.x4.trans.shared.b16 {%0,%1,%2,%3}, [%4];" \
        : "=r"(r0), "=r"(r1), "=r"(r2), "=r"(r3) : "r"(addr))

#define MMA16816(d, a, b) \
    asm volatile("mma.sync.aligned.m16n8k16.row.col.f32.bf16.bf16.f32 " \
        "{%0,%1,%2,%3}, {%4,%5,%6,%7}, {%8,%9}, {%0,%1,%2,%3};" \
        : "+f"((d)[0]), "+f"((d)[1]), "+f"((d)[2]), "+f"((d)[3]) \
        : "r"((a)[0]), "r"((a)[1]), "r"((a)[2]), "r"((a)[3]), \
          "r"((b)[0]), "r"((b)[1]))

__device__ __forceinline__ void split1(float v, __nv_bfloat16& h, __nv_bfloat16& l) {
    h = __float2bfloat16_rn(v);
    l = __float2bfloat16_rn(v - __bfloat162float(h));
}

// ---------------- elementwise split (video input) ----------------
__global__ __launch_bounds__(256)
void split_k(const float4* __restrict__ src, __nv_bfloat162* __restrict__ hi,
             __nv_bfloat162* __restrict__ lo, int n4)
{
    for (int i = blockIdx.x * 256 + threadIdx.x; i < n4; i += gridDim.x * 256) {
        float4 v = src[i];
        __nv_bfloat16 h0, h1, h2, h3, l0, l1, l2, l3;
        split1(v.x, h0, l0); split1(v.y, h1, l1);
        split1(v.z, h2, l2); split1(v.w, h3, l3);
        hi[i * 2 + 0] = __nv_bfloat162(h0, h1);
        hi[i * 2 + 1] = __nv_bfloat162(h2, h3);
        lo[i * 2 + 0] = __nv_bfloat162(l0, l1);
        lo[i * 2 + 1] = __nv_bfloat162(l2, l3);
    }
}

// ---------------- fused weight conversion (single launch) ----------------
__device__ __forceinline__ void tsplit_tile(const float* __restrict__ W,
                                            __nv_bfloat16* __restrict__ hi,
                                            __nv_bfloat16* __restrict__ lo,
                                            int K, int N, int t)
{
    __shared__ float tile[32][33];
    int ntN = N >> 5;
    int n0 = (t % ntN) << 5, k0 = (t / ntN) << 5;
    int tid = threadIdx.x;
    int c = tid & 31;
#pragma unroll
    for (int i = 0; i < 4; i++) {
        int r = (tid >> 5) + i * 8;
        tile[r][c] = W[(size_t)(k0 + r) * N + n0 + c];
    }
    __syncthreads();
#pragma unroll
    for (int i = 0; i < 4; i++) {
        int rr = (tid >> 5) + i * 8;
        float v = tile[c][rr];
        __nv_bfloat16 h, l;
        split1(v, h, l);
        size_t o = (size_t)(n0 + rr) * K + k0 + c;
        hi[o] = h;
        lo[o] = l;
    }
}

// grid = 6668 blocks of 256
__global__ __launch_bounds__(256)
void convert_all(const float* __restrict__ Wv,
                 const float* __restrict__ Wq, const float* __restrict__ Wk,
                 const float* __restrict__ Wva, const float* __restrict__ Wo,
                 const float* __restrict__ W1, const float* __restrict__ W2,
                 const float* __restrict__ bq, const float* __restrict__ bk,
                 const float* __restrict__ bv,
                 __nv_bfloat16* __restrict__ wvh, __nv_bfloat16* __restrict__ wvl,
                 __nv_bfloat16* __restrict__ wqkvh, __nv_bfloat16* __restrict__ wqkvl,
                 __nv_bfloat16* __restrict__ woh, __nv_bfloat16* __restrict__ wol,
                 __nv_bfloat16* __restrict__ w1h, __nv_bfloat16* __restrict__ w1l,
                 __nv_bfloat16* __restrict__ w2h, __nv_bfloat16* __restrict__ w2l,
                 float* __restrict__ bqkv)
{
    int t = blockIdx.x;
    if (t < 512) { tsplit_tile(Wv, wvh, wvl, 1024, 512, t); return; }
    t -= 512;
    if (t < 6144) {
        int i = t / 3072, u = t % 3072;
        size_t od = (size_t)i * 512 * 512;
        size_t oq = (size_t)i * QKVN * 512;
        size_t of = (size_t)i * 512 * 2048;
        if (u < 256)        tsplit_tile(Wq  + od, wqkvh + oq,              wqkvl + oq,              512, 512, u);
        else if (u < 512)   tsplit_tile(Wk  + od, wqkvh + oq + 262144,     wqkvl + oq + 262144,     512, 512, u - 256);
        else if (u < 768)   tsplit_tile(Wva + od, wqkvh + oq + 524288,     wqkvl + oq + 524288,     512, 512, u - 512);
        else if (u < 1024)  tsplit_tile(Wo  + od, woh + od, wol + od, 512, 512, u - 768);
        else if (u < 2048)  tsplit_tile(W1 + of, w1h + of, w1l + of, 512, 2048, u - 1024);
        else                tsplit_tile(W2 + of, w2h + of, w2l + of, 2048, 512, u - 2048);
        return;
    }
    t -= 6144;
    int idx = t * 256 + threadIdx.x;      // 0..3071
    if (idx < 2 * QKVN) {
        int i = idx / QKVN, j = idx % QKVN;
        float v = (j < 512) ? bq[i * 512 + j]
                : (j < 1024) ? bk[i * 512 + j - 512]
                : bv[i * 512 + j - 1024];
        bqkv[idx] = v;
    }
}

// ---------------- mma.sync split-bf16 GEMM (2-stage, 2 CTA/SM) ----------------
#define MG_ROWH 40
#define MG_MATH (128 * MG_ROWH)
#define MG_MATB (MG_MATH * 2)
#define MG_STGB (4 * MG_MATB)
#define MG_SMEM (2 * MG_STGB)     // 81920 -> 2 CTAs/SM

__device__ __forceinline__ void mg_load(uint32_t s0,
    const __nv_bfloat16* __restrict__ Ah, const __nv_bfloat16* __restrict__ Al,
    const __nv_bfloat16* __restrict__ Bh, const __nv_bfloat16* __restrict__ Bl,
    int bm, int bn, int K, int k0, int tid)
{
#pragma unroll
    for (int i = 0; i < 2; i++) {
        int u = tid + (i << 8);
        int r = u >> 2, c8 = (u & 3) << 3;
        size_t ga = (size_t)(bm + r) * K + k0 + c8;
        size_t gb = (size_t)(bn + r) * K + k0 + c8;
        uint32_t s = s0 + (uint32_t)(r * MG_ROWH + c8) * 2;
        cp16(s,               Ah + ga);
        cp16(s + MG_MATB,     Al + ga);
        cp16(s + 2 * MG_MATB, Bh + gb);
        cp16(s + 3 * MG_MATB, Bl + gb);
    }
}

template<bool GELU, bool RES, bool SPLIT>
__global__ __launch_bounds__(256, 2)
void mgemm(const __nv_bfloat16* __restrict__ Ah, const __nv_bfloat16* __restrict__ Al,
           const __nv_bfloat16* __restrict__ Bh, const __nv_bfloat16* __restrict__ Bl,
           const float* __restrict__ bias, const float* __restrict__ res,
           float* __restrict__ C, __nv_bfloat16* __restrict__ Ch,
           __nv_bfloat16* __restrict__ Cl, int M, int N, int K)
{
    extern __shared__ char smem[];
    const uint32_t sbase = smem_u32(smem);
    const int tid = threadIdx.x;
    const int lane = tid & 31, wid = tid >> 5;
    const int wm = wid >> 1, wn = wid & 1;
    const int bn = blockIdx.x * 128, bm = blockIdx.y * 128;

    float acc[2][8][4];
#pragma unroll
    for (int i = 0; i < 2; i++)
#pragma unroll
        for (int j = 0; j < 8; j++)
#pragma unroll
            for (int p = 0; p < 4; p++) acc[i][j][p] = 0.f;

    const int a_r  = (lane < 16) ? lane : (lane - 16);
    const int a_k  = (lane < 16) ? 0 : 8;
    const int b_r  = ((lane >> 4) << 3) + (lane & 7);
    const int b_k  = ((lane >> 3) & 1) << 3;

    mg_load(sbase, Ah, Al, Bh, Bl, bm, bn, K, 0, tid);
    CP_COMMIT();

    const int NC = K >> 5;
    for (int c = 0; c < NC; c++) {
        if (c + 1 < NC) {
            mg_load(sbase + ((c + 1) & 1) * MG_STGB, Ah, Al, Bh, Bl,
                    bm, bn, K, (c + 1) << 5, tid);
            CP_COMMIT();
            CP_WAIT1();
        } else {
            CP_WAIT0();
        }
        __syncthreads();

        const uint32_t s0  = sbase + (c & 1) * MG_STGB;
        const uint32_t aH  = s0;
        const uint32_t aL  = s0 + MG_MATB;
        const uint32_t bH  = s0 + 2 * MG_MATB;
        const uint32_t bL  = s0 + 3 * MG_MATB;

#pragma unroll
        for (int ks = 0; ks < 2; ks++) {
            uint32_t bhf[8][2], blf[8][2];
#pragma unroll
            for (int nb2 = 0; nb2 < 4; nb2++) {
                int row = wn * 64 + nb2 * 16 + b_r;
                int kof = ks * 16 + b_k;
                uint32_t off = (uint32_t)(row * MG_ROWH + kof) * 2;
                uint32_t r0, r1, r2, r3;
                LDSM4(r0, r1, r2, r3, bH + off);
                bhf[nb2 * 2][0] = r0; bhf[nb2 * 2][1] = r1;
                bhf[nb2 * 2 + 1][0] = r2; bhf[nb2 * 2 + 1][1] = r3;
                LDSM4(r0, r1, r2, r3, bL + off);
                blf[nb2 * 2][0] = r0; blf[nb2 * 2][1] = r1;
                blf[nb2 * 2 + 1][0] = r2; blf[nb2 * 2 + 1][1] = r3;
            }
#pragma unroll
            for (int mh = 0; mh < 2; mh++) {
                int row = wm * 32 + mh * 16 + a_r;
                int kof = ks * 16 + a_k;
                uint32_t off = (uint32_t)(row * MG_ROWH + kof) * 2;
                uint32_t ahf[4], alf[4];
                LDSM4(ahf[0], ahf[1], ahf[2], ahf[3], aH + off);
                LDSM4(alf[0], alf[1], alf[2], alf[3], aL + off);
#pragma unroll
                for (int nb = 0; nb < 8; nb++) {
                    MMA16816(acc[mh][nb], ahf, bhf[nb]);
                    MMA16816(acc[mh][nb], ahf, blf[nb]);
                    MMA16816(acc[mh][nb], alf, bhf[nb]);
                }
            }
        }
        __syncthreads();
    }

    const int g = lane >> 2, t4 = lane & 3;
#pragma unroll
    for (int mh = 0; mh < 2; mh++) {
#pragma unroll
        for (int nb = 0; nb < 8; nb++) {
            int col = bn + wn * 64 + nb * 8 + t4 * 2;
            float b0 = bias[col], b1 = bias[col + 1];
#pragma unroll
            for (int hf = 0; hf < 2; hf++) {
                int row = bm + wm * 32 + mh * 16 + g + hf * 8;
                float v0 = acc[mh][nb][hf * 2 + 0] + b0;
                float v1 = acc[mh][nb][hf * 2 + 1] + b1;
                if (RES) {
                    float2 rv = *(const float2*)(res + (size_t)row * N + col);
                    v0 += rv.x; v1 += rv.y;
                }
                if (GELU) {
                    v0 = 0.5f * v0 * (1.0f + erff(v0 * 0.70710678118654752f));
                    v1 = 0.5f * v1 * (1.0f + erff(v1 * 0.70710678118654752f));
                }
                if (SPLIT) {
                    __nv_bfloat16 h0, h1, l0, l1;
                    split1(v0, h0, l0);
                    split1(v1, h1, l1);
                    size_t o = (size_t)row * N + col;
                    *(__nv_bfloat162*)(Ch + o) = __nv_bfloat162(h0, h1);
                    *(__nv_bfloat162*)(Cl + o) = __nv_bfloat162(l0, l1);
                } else {
                    *(float2*)(C + (size_t)row * N + col) = make_float2(v0, v1);
                }
            }
        }
    }
}

// ---------------- block reduction ----------------
__device__ __forceinline__ float block_sum256(float v, float* red) {
    int lane = threadIdx.x & 31;
    int w    = threadIdx.x >> 5;
#pragma unroll
    for (int o = 16; o > 0; o >>= 1) v += __shfl_xor_sync(0xffffffffu, v, o);
    if (lane == 0) red[w] = v;
    __syncthreads();
    if (w == 0) {
        float r = (lane < 8) ? red[lane] : 0.f;
#pragma unroll
        for (int o = 4; o > 0; o >>= 1) r += __shfl_xor_sync(0xffffffffu, r, o);
        if (lane == 0) red[0] = r;
    }
    __syncthreads();
    float out = red[0];
    __syncthreads();
    return out;
}

// ---------------- LayerNorm over D=512 + optional split output ----------------
template<bool SPLIT>
__global__ __launch_bounds__(256)
void ln512(const float* __restrict__ in, const float* __restrict__ g,
           const float* __restrict__ b, float* __restrict__ out,
           __nv_bfloat16* __restrict__ oh, __nv_bfloat16* __restrict__ ol)
{
    __shared__ float red[32];
    size_t row = blockIdx.x;
    const float* x = in + row * D_;
    int c0 = threadIdx.x, c1 = threadIdx.x + 256;
    float v0 = x[c0], v1 = x[c1];
    float mean = block_sum256(v0 + v1, red) * (1.f / 512.f);
    float d0 = v0 - mean, d1 = v1 - mean;
    float var = block_sum256(d0 * d0 + d1 * d1, red) * (1.f / 512.f);
    float inv = 1.f / sqrtf(var + 1e-12f);
    float r0 = d0 * inv * g[c0] + b[c0];
    float r1 = d1 * inv * g[c1] + b[c1];
    out[row * D_ + c0] = r0;
    out[row * D_ + c1] = r1;
    if (SPLIT) {
        __nv_bfloat16 h0, h1, l0, l1;
        split1(r0, h0, l0);
        split1(r1, h1, l1);
        oh[row * D_ + c0] = h0; oh[row * D_ + c1] = h1;
        ol[row * D_ + c0] = l0; ol[row * D_ + c1] = l1;
    }
}

// ---------------- assemble x = LN(concat(q, v) + pos + mod), split out ----------------
__global__ __launch_bounds__(256)
void assemble_ln(const float* __restrict__ question, const float* __restrict__ vproj,
                 const float* __restrict__ pos, const float* __restrict__ mod,
                 const float* __restrict__ g, const float* __restrict__ bb,
                 float* __restrict__ out, __nv_bfloat16* __restrict__ oh,
                 __nv_bfloat16* __restrict__ ol)
{
    __shared__ float red[32];
    int row = blockIdx.x;
    int b = row >> 9, s = row & 511;
    int c0 = threadIdx.x, c1 = threadIdx.x + 256;
    float v0, v1;
    if (s < Q_) {
        const float* src = question + ((size_t)b * Q_ + s) * D_;
        v0 = src[c0]; v1 = src[c1];
    } else {
        const float* src = vproj + ((size_t)b * T_ + (s - Q_)) * D_;
        v0 = src[c0]; v1 = src[c1];
    }
    const float* me = mod + (s < Q_ ? 0 : 1) * D_;
    v0 += pos[s * D_ + c0] + me[c0];
    v1 += pos[s * D_ + c1] + me[c1];
    float mean = block_sum256(v0 + v1, red) * (1.f / 512.f);
    float d0 = v0 - mean, d1 = v1 - mean;
    float var = block_sum256(d0 * d0 + d1 * d1, red) * (1.f / 512.f);
    float inv = 1.f / sqrtf(var + 1e-12f);
    float r0 = d0 * inv * g[c0] + bb[c0];
    float r1 = d1 * inv * g[c1] + bb[c1];
    size_t o = (size_t)row * D_;
    out[o + c0] = r0;
    out[o + c1] = r1;
    __nv_bfloat16 h0, h1, l0, l1;
    split1(r0, h0, l0);
    split1(r1, h1, l1);
    oh[o + c0] = h0; oh[o + c1] = h1;
    ol[o + c0] = l0; ol[o + c1] = l1;
}

// ---------------- mma.sync flash attention (split bf16, single KV buffer) ----------------
#define AT_ST 72
#define AT_MATB (64 * AT_ST * 2)     // 9216 bytes per matrix tile
#define ATTN_SMEM (6 * AT_MATB + 256)

__global__ __launch_bounds__(128, 4)
void attn_mma(const __nv_bfloat16* __restrict__ QKVh, const __nv_bfloat16* __restrict__ QKVl,
              const int* __restrict__ mask,
              __nv_bfloat16* __restrict__ Oh, __nv_bfloat16* __restrict__ Ol)
{
    extern __shared__ char sm8[];
    const uint32_t sb = smem_u32(sm8);
    const uint32_t sQH = sb, sQL = sb + AT_MATB;
    const uint32_t sKH = sb + 2 * AT_MATB, sKL = sb + 3 * AT_MATB;
    const uint32_t sVH = sb + 4 * AT_MATB, sVL = sb + 5 * AT_MATB;
    int* maskS = (int*)(sm8 + 6 * AT_MATB);

    const int qt = blockIdx.x, h = blockIdx.y, b = blockIdx.z;
    const int tid = threadIdx.x, lane = tid & 31, wq = tid >> 5;
    const int g = lane >> 2, t4 = lane & 3;

    const int a_r = (lane < 16) ? lane : lane - 16;
    const int a_k = (lane < 16) ? 0 : 8;
    const int b_r = ((lane >> 4) << 3) + (lane & 7);
    const int b_k = ((lane >> 3) & 1) << 3;
    const int v_r = (lane & 7) + (((lane >> 3) & 1) << 3);
    const int v_n = ((lane >> 4) & 1) << 3;

    // load Q tile (hi+lo): 64 rows x 64 halves
#pragma unroll
    for (int i = 0; i < 4; i++) {
        int u = tid + i * 128;
        int r = u >> 3, c8 = (u & 7) << 3;
        size_t gofs = (size_t)(b * S_ + qt * 64 + r) * QKVN + h * DH_ + c8;
        uint32_t so = (uint32_t)(r * AT_ST + c8) * 2;
        cp16(sQH + so, QKVh + gofs);
        cp16(sQL + so, QKVl + gofs);
    }
    CP_COMMIT();

    float oacc[8][4];
#pragma unroll
    for (int i = 0; i < 8; i++)
#pragma unroll
        for (int j = 0; j < 4; j++) oacc[i][j] = 0.f;
    float m0 = NEG_INF, m1 = NEG_INF, l0 = 0.f, l1 = 0.f;

    for (int kt = 0; kt < 8; kt++) {
        __syncthreads();
#pragma unroll
        for (int i = 0; i < 4; i++) {
            int u = tid + i * 128;
            int r = u >> 3, c8 = (u & 7) << 3;
            size_t grow = (size_t)(b * S_ + kt * 64 + r) * QKVN + h * DH_;
            uint32_t so = (uint32_t)(r * AT_ST + c8) * 2;
            cp16(sKH + so, QKVh + grow + 512 + c8);
            cp16(sKL + so, QKVl + grow + 512 + c8);
            cp16(sVH + so, QKVh + grow + 1024 + c8);
            cp16(sVL + so, QKVl + grow + 1024 + c8);
        }
        if (tid < 64) maskS[tid] = mask[b * S_ + kt * 64 + tid];
        CP_COMMIT();
        CP_WAIT0();
        __syncthreads();

        // ---- scores: S = Q K^T (split, 3 MMA) ----
        float sacc[8][4];
#pragma unroll
        for (int i = 0; i < 8; i++)
#pragma unroll
            for (int j = 0; j < 4; j++) sacc[i][j] = 0.f;

#pragma unroll
        for (int ks = 0; ks < 4; ks++) {
            uint32_t qh[4], ql[4];
            uint32_t qoff = (uint32_t)((wq * 16 + a_r) * AT_ST + ks * 16 + a_k) * 2;
            LDSM4(qh[0], qh[1], qh[2], qh[3], sQH + qoff);
            LDSM4(ql[0], ql[1], ql[2], ql[3], sQL + qoff);
#pragma unroll
            for (int nb2 = 0; nb2 < 4; nb2++) {
                uint32_t kh[4], kl[4];
                uint32_t koff = (uint32_t)((nb2 * 16 + b_r) * AT_ST + ks * 16 + b_k) * 2;
                LDSM4(kh[0], kh[1], kh[2], kh[3], sKH + koff);
                LDSM4(kl[0], kl[1], kl[2], kl[3], sKL + koff);
                uint32_t f0[2] = {kh[0], kh[1]}, f1[2] = {kh[2], kh[3]};
                uint32_t e0[2] = {kl[0], kl[1]}, e1[2] = {kl[2], kl[3]};
                MMA16816(sacc[nb2 * 2],     qh, f0);
                MMA16816(sacc[nb2 * 2],     qh, e0);
                MMA16816(sacc[nb2 * 2],     ql, f0);
                MMA16816(sacc[nb2 * 2 + 1], qh, f1);
                MMA16816(sacc[nb2 * 2 + 1], qh, e1);
                MMA16816(sacc[nb2 * 2 + 1], ql, f1);
            }
        }

        // ---- scale + mask ----
#pragma unroll
        for (int nb = 0; nb < 8; nb++) {
            int c = (nb << 3) + (t4 << 1);
            bool z0 = (maskS[c] == 0), z1 = (maskS[c + 1] == 0);
            sacc[nb][0] = z0 ? NEG_INF : sacc[nb][0] * 0.125f;
            sacc[nb][1] = z1 ? NEG_INF : sacc[nb][1] * 0.125f;
            sacc[nb][2] = z0 ? NEG_INF : sacc[nb][2] * 0.125f;
            sacc[nb][3] = z1 ? NEG_INF : sacc[nb][3] * 0.125f;
        }

        // ---- online softmax (rows g and g+8) ----
        float t0 = NEG_INF, t1 = NEG_INF;
#pragma unroll
        for (int nb = 0; nb < 8; nb++) {
            t0 = fmaxf(t0, fmaxf(sacc[nb][0], sacc[nb][1]));
            t1 = fmaxf(t1, fmaxf(sacc[nb][2], sacc[nb][3]));
        }
        t0 = fmaxf(t0, __shfl_xor_sync(0xffffffffu, t0, 1));
        t0 = fmaxf(t0, __shfl_xor_sync(0xffffffffu, t0, 2));
        t1 = fmaxf(t1, __shfl_xor_sync(0xffffffffu, t1, 1));
        t1 = fmaxf(t1, __shfl_xor_sync(0xffffffffu, t1, 2));
        float m0n = fmaxf(m0, t0), m1n = fmaxf(m1, t1);
        float me0 = (m0n == NEG_INF) ? 0.f : m0n;
        float me1 = (m1n == NEG_INF) ? 0.f : m1n;
        float alpha0 = __expf(m0 - me0);
        float alpha1 = __expf(m1 - me1);
        m0 = m0n; m1 = m1n;

        float s0 = 0.f, s1 = 0.f;
#pragma unroll
        for (int nb = 0; nb < 8; nb++) {
            float p0 = (sacc[nb][0] == NEG_INF) ? 0.f : __expf(sacc[nb][0] - me0);
            float p1 = (sacc[nb][1] == NEG_INF) ? 0.f : __expf(sacc[nb][1] - me0);
            float p2 = (sacc[nb][2] == NEG_INF) ? 0.f : __expf(sacc[nb][2] - me1);
            float p3 = (sacc[nb][3] == NEG_INF) ? 0.f : __expf(sacc[nb][3] - me1);
            sacc[nb][0] = p0; sacc[nb][1] = p1; sacc[nb][2] = p2; sacc[nb][3] = p3;
            s0 += p0 + p1; s1 += p2 + p3;
        }
        s0 += __shfl_xor_sync(0xffffffffu, s0, 1);
        s0 += __shfl_xor_sync(0xffffffffu, s0, 2);
        s1 += __shfl_xor_sync(0xffffffffu, s1, 1);
        s1 += __shfl_xor_sync(0xffffffffu, s1, 2);
        l0 = l0 * alpha0 + s0;
        l1 = l1 * alpha1 + s1;
#pragma unroll
        for (int nb = 0; nb < 8; nb++) {
            oacc[nb][0] *= alpha0; oacc[nb][1] *= alpha0;
            oacc[nb][2] *= alpha1; oacc[nb][3] *= alpha1;
        }

        // ---- O += P V (split P, split V, 3 MMA) ----
#pragma unroll
        for (int ks = 0; ks < 4; ks++) {
            const float* sa = sacc[2 * ks];
            const float* sc = sacc[2 * ks + 1];
            uint32_t ph[4], pl[4];
            {
                __nv_bfloat16 h0, l0b, h1, l1b;
                split1(sa[0], h0, l0b); split1(sa[1], h1, l1b);
                ph[0] = ((uint32_t)*(uint16_t*)&h1 << 16) | *(uint16_t*)&h0;
                pl[0] = ((uint32_t)*(uint16_t*)&l1b << 16) | *(uint16_t*)&l0b;
                split1(sa[2], h0, l0b); split1(sa[3], h1, l1b);
                ph[1] = ((uint32_t)*(uint16_t*)&h1 << 16) | *(uint16_t*)&h0;
                pl[1] = ((uint32_t)*(uint16_t*)&l1b << 16) | *(uint16_t*)&l0b;
                split1(sc[0], h0, l0b); split1(sc[1], h1, l1b);
                ph[2] = ((uint32_t)*(uint16_t*)&h1 << 16) | *(uint16_t*)&h0;
                pl[2] = ((uint32_t)*(uint16_t*)&l1b << 16) | *(uint16_t*)&l0b;
                split1(sc[2], h0, l0b); split1(sc[3], h1, l1b);
                ph[3] = ((uint32_t)*(uint16_t*)&h1 << 16) | *(uint16_t*)&h0;
                pl[3] = ((uint32_t)*(uint16_t*)&l1b << 16) | *(uint16_t*)&l0b;
            }
#pragma unroll
            for (int nb2 = 0; nb2 < 4; nb2++) {
                uint32_t vh[4], vl[4];
                uint32_t voff = (uint32_t)((ks * 16 + v_r) * AT_ST + nb2 * 16 + v_n) * 2;
                LDSM4T(vh[0], vh[1], vh[2], vh[3], sVH + voff);
                LDSM4T(vl[0], vl[1], vl[2], vl[3], sVL + voff);
                uint32_t f0[2] = {vh[0], vh[1]}, f1[2] = {vh[2], vh[3]};
                uint32_t e0[2] = {vl[0], vl[1]}, e1[2] = {vl[2], vl[3]};
                MMA16816(oacc[nb2 * 2],     ph, f0);
                MMA16816(oacc[nb2 * 2],     ph, e0);
                MMA16816(oacc[nb2 * 2],     pl, f0);
                MMA16816(oacc[nb2 * 2 + 1], ph, f1);
                MMA16816(oacc[nb2 * 2 + 1], ph, e1);
                MMA16816(oacc[nb2 * 2 + 1], pl, f1);
            }
        }
    }

    // ---- epilogue: O/l, split, store ctx ----
    float inv0 = 1.f / l0, inv1 = 1.f / l1;
    int row0 = b * S_ + qt * 64 + wq * 16 + g;
#pragma unroll
    for (int nb = 0; nb < 8; nb++) {
        int col = h * DH_ + nb * 8 + t4 * 2;
        float v0 = oacc[nb][0] * inv0, v1 = oacc[nb][1] * inv0;
        float v2 = oacc[nb][2] * inv1, v3 = oacc[nb][3] * inv1;
        __nv_bfloat16 h0, l0b, h1, l1b;
        split1(v0, h0, l0b); split1(v1, h1, l1b);
        *(__nv_bfloat162*)(Oh + (size_t)row0 * D_ + col) = __nv_bfloat162(h0, h1);
        *(__nv_bfloat162*)(Ol + (size_t)row0 * D_ + col) = __nv_bfloat162(l0b, l1b);
        split1(v2, h0, l0b); split1(v3, h1, l1b);
        *(__nv_bfloat162*)(Oh + (size_t)(row0 + 8) * D_ + col) = __nv_bfloat162(h0, h1);
        *(__nv_bfloat162*)(Ol + (size_t)(row0 + 8) * D_ + col) = __nv_bfloat162(l0b, l1b);
    }
}

// ---------------- orchestration ----------------
extern "C" void kernel_launch(void* const* d_in, const int* in_sizes, int n_in,
                              void* d_out, int out_size)
{
    (void)in_sizes; (void)n_in; (void)out_size;
    const float* video    = (const float*)d_in[0];
    const float* question = (const float*)d_in[1];
    const int*   mask     = (const int*)  d_in[2];
    const float* pos_emb  = (const float*)d_in[3];
    const float* mod_emb  = (const float*)d_in[4];
    const float* Wv   = (const float*)d_in[5];
    const float* bv   = (const float*)d_in[6];
    const float* nv_g = (const float*)d_in[7];
    const float* nv_b = (const float*)d_in[8];
    const float* emb_g= (const float*)d_in[9];
    const float* emb_b= (const float*)d_in[10];
    const float* Wq   = (const float*)d_in[11];
    const float* bq   = (const float*)d_in[12];
    const float* Wk   = (const float*)d_in[13];
    const float* bk   = (const float*)d_in[14];
    const float* Wva  = (const float*)d_in[15];
    const float* bva  = (const float*)d_in[16];
    const float* Wo   = (const float*)d_in[17];
    const float* bo   = (const float*)d_in[18];
    const float* ln1_g= (const float*)d_in[19];
    const float* ln1_b= (const float*)d_in[20];
    const float* W1   = (const float*)d_in[21];
    const float* b1   = (const float*)d_in[22];
    const float* W2   = (const float*)d_in[23];
    const float* b2   = (const float*)d_in[24];
    const float* ln2_g= (const float*)d_in[25];
    const float* ln2_b= (const float*)d_in[26];

    float *x, *t, *bqkv;
    cudaGetSymbolAddress((void**)&x, g_x);
    cudaGetSymbolAddress((void**)&t, g_t);
    cudaGetSymbolAddress((void**)&bqkv, g_bqkv);

    __nv_bfloat16 *ah, *al, *bh, *bl, *qkvh, *qkvl, *wvh, *wvl, *wqkvh, *wqkvl,
                  *woh, *wol, *w1h, *w1l, *w2h, *w2l;
    cudaGetSymbolAddress((void**)&ah,    g_ah);
    cudaGetSymbolAddress((void**)&al,    g_al);
    cudaGetSymbolAddress((void**)&bh,    g_bh);
    cudaGetSymbolAddress((void**)&bl,    g_bl);
    cudaGetSymbolAddress((void**)&qkvh,  g_qkvh);
    cudaGetSymbolAddress((void**)&qkvl,  g_qkvl);
    cudaGetSymbolAddress((void**)&wvh,   g_wvh);
    cudaGetSymbolAddress((void**)&wvl,   g_wvl);
    cudaGetSymbolAddress((void**)&wqkvh, g_wqkvh);
    cudaGetSymbolAddress((void**)&wqkvl, g_wqkvl);
    cudaGetSymbolAddress((void**)&woh,   g_woh);
    cudaGetSymbolAddress((void**)&wol,   g_wol);
    cudaGetSymbolAddress((void**)&w1h,   g_w1h);
    cudaGetSymbolAddress((void**)&w1l,   g_w1l);
    cudaGetSymbolAddress((void**)&w2h,   g_w2h);
    cudaGetSymbolAddress((void**)&w2l,   g_w2l);

    cudaFuncSetAttribute(attn_mma, cudaFuncAttributeMaxDynamicSharedMemorySize, ATTN_SMEM);
    cudaFuncSetAttribute(mgemm<false, false, false>, cudaFuncAttributeMaxDynamicSharedMemorySize, MG_SMEM);
    cudaFuncSetAttribute(mgemm<false, true,  false>, cudaFuncAttributeMaxDynamicSharedMemorySize, MG_SMEM);
    cudaFuncSetAttribute(mgemm<true,  false, true >, cudaFuncAttributeMaxDynamicSharedMemorySize, MG_SMEM);
    cudaFuncSetAttribute(mgemm<false, false, true >, cudaFuncAttributeMaxDynamicSharedMemorySize, MG_SMEM);

    // all weight conversion in ONE launch
    convert_all<<<6668, 256>>>(Wv, Wq, Wk, Wva, Wo, W1, W2, bq, bk, bva,
                               wvh, wvl, wqkvh, wqkvl, woh, wol,
                               w1h, w1l, w2h, w2l, bqkv);

    // video split, video projection, LN(nv), assemble
    split_k<<<2048, 256>>>((const float4*)video, (__nv_bfloat162*)ah,
                           (__nv_bfloat162*)al, (int)((size_t)VROWS * FD_ / 4));
    mgemm<false, false, false><<<dim3(D_ / 128, VROWS / 128), 256, MG_SMEM>>>(
        ah, al, wvh, wvl, bv, nullptr, t, nullptr, nullptr, VROWS, D_, FD_);
    ln512<false><<<VROWS, 256>>>(t, nv_g, nv_b, t, nullptr, nullptr);
    assemble_ln<<<NROWS, 256>>>(question, t, pos_emb, mod_emb, emb_g, emb_b, x, ah, al);

    for (int i = 0; i < 2; i++) {
        size_t od = (size_t)i * 512 * 512;
        size_t oq = (size_t)i * QKVN * 512;
        size_t of = (size_t)i * 512 * 2048;
        const float* boi = bo + i * D_;
        const float* b1i = b1 + i * FF_;
        const float* b2i = b2 + i * D_;

        // fused QKV projection (split output)
        mgemm<false, false, true><<<dim3(QKVN / 128, NROWS / 128), 256, MG_SMEM>>>(
            ah, al, wqkvh + oq, wqkvl + oq, bqkv + i * QKVN, nullptr,
            nullptr, qkvh, qkvl, NROWS, QKVN, D_);

        // attention -> ctx split (bh/bl viewed [NROWS, D])
        attn_mma<<<dim3(S_ / 64, H_, B_), 128, ATTN_SMEM>>>(qkvh, qkvl, mask, bh, bl);

        // output projection + residual, LN1 (-> x fp32 + ah/al split)
        mgemm<false, true, false><<<dim3(4, NROWS / 128), 256, MG_SMEM>>>(
            bh, bl, woh + od, wol + od, boi, x, t, nullptr, nullptr, NROWS, D_, D_);
        ln512<true><<<NROWS, 256>>>(t, ln1_g + i * D_, ln1_b + i * D_, x, ah, al);

        // FFN
        mgemm<true, false, true><<<dim3(FF_ / 128, NROWS / 128), 256, MG_SMEM>>>(
            ah, al, w1h + of, w1l + of, b1i, nullptr, nullptr, bh, bl, NROWS, FF_, D_);
        mgemm<false, true, false><<<dim3(4, NROWS / 128), 256, MG_SMEM>>>(
            bh, bl, w2h + of, w2l + of, b2i, x, t, nullptr, nullptr, NROWS, D_, FF_);

        float* out = (i == 1) ? (float*)d_out : x;
        ln512<true><<<NROWS, 256>>>(t, ln2_g + i * D_, ln2_b + i * D_, out, ah, al);
    }
}